// round 10
// baseline (speedup 1.0000x reference)
#include <cuda_runtime.h>

#define NT      256
#define NBINS   10
#define STAGES  4

__device__ float    g_sum[NBINS];
__device__ float    g_cnt[NBINS];
__device__ unsigned g_done;

// Dynamic smem layout (bytes):
//   [0, 16384)        outputs stages: STAGES * NT * 16
//   [16384, 24576)    targets stages: STAGES * NT * 8
//   [24576, 45056)    hist[NBINS][NT] float2  (bin stride 2048B -> conflict-free)
//   [45056, 45136)    s_red[20]
//   [45136, 45140)    s_last
#define OUTS_OFF 0
#define TGTS_OFF (STAGES * NT * 16)
#define HIST_OFF (TGTS_OFF + STAGES * NT * 8)
#define RED_OFF  (HIST_OFF + NBINS * NT * 8)
#define SMEM_BYTES (RED_OFF + 96)

extern __shared__ char smem[];

__device__ __forceinline__ unsigned smem_addr(unsigned off) {
    unsigned base;
    asm("{ .reg .u64 a; cvta.to.shared.u64 a, %1; cvt.u32.u64 %0, a; }"
        : "=r"(base) : "l"((void*)smem));
    return base + off;
}

// Per-sample: d = x_other - x_target
//   v = 1 + e^d ; l = log2(v) ; r = 1/v ; bin = floor(20 - 20r); valid <=> bin < 10
__device__ __forceinline__ void process(float dd, unsigned t, unsigned hbase) {
    float d = __int_as_float(__float_as_int(dd) ^ (int)(t << 31));
    float u; asm("ex2.approx.f32 %0, %1;" : "=f"(u) : "f"(d * 1.4426950408889634f));
    float v = 1.0f + u;
    float l; asm("lg2.approx.f32 %0, %1;" : "=f"(l) : "f"(v));
    float r; asm("rcp.approx.f32 %0, %1;" : "=f"(r) : "f"(v));
    float s = fmaf(-20.0f, r, 20.0f);
    int b = (int)s;                       // trunc; in [0,20]
    unsigned long long lv;
    asm("mov.b64 %0, {%1, %2};" : "=l"(lv) : "f"(l), "f"(1.0f));
    unsigned addr = hbase + ((unsigned)b << 11);
    asm volatile("{\n\t.reg .pred p;\n\t.reg .b64 hv;\n\t"
                 "setp.lt.s32 p, %0, 10;\n\t"
                 "@p ld.shared.b64 hv, [%1];\n\t"
                 "@p add.rn.f32x2 hv, hv, %2;\n\t"
                 "@p st.shared.b64 [%1], hv;\n\t}"
                 :: "r"(b), "r"(addr), "l"(lv) : "memory");
}

__device__ __forceinline__ void stage_in(unsigned so, unsigned st,
                                         const float4* o4, const uint2* t2, int idx) {
    asm volatile("cp.async.cg.shared.global [%0], [%1], 16;" :: "r"(so), "l"(o4 + idx));
    asm volatile("cp.async.ca.shared.global [%0], [%1], 8;"  :: "r"(st), "l"(t2 + idx));
    asm volatile("cp.async.commit_group;" ::: "memory");
}

__global__ void __launch_bounds__(NT)
ghm_main(const float4* __restrict__ o4, const uint2* __restrict__ t2,
         int npairs, int n, const float* __restrict__ acc_sum,
         float* __restrict__ out, int ncta) {
    const int tid = threadIdx.x;

    float*    s_red  = (float*)(smem + RED_OFF);
    unsigned* s_last = (unsigned*)(smem + RED_OFF + 80);
    float2*   hist   = (float2*)(smem + HIST_OFF);

    if (tid < 2 * NBINS) s_red[tid] = 0.0f;
#pragma unroll
    for (int k = 0; k < NBINS; k++) hist[k * NT + tid] = make_float2(0.0f, 0.0f);
    __syncthreads();

    const unsigned hbase = smem_addr(HIST_OFF) + tid * 8;
    const unsigned obase = smem_addr(OUTS_OFF) + tid * 16;
    const unsigned tbase = smem_addr(TGTS_OFF) + tid * 8;

    const int stride = gridDim.x * blockDim.x;
    const int gbase  = blockIdx.x * blockDim.x + tid;
    const int F = npairs / stride;        // full iterations (all threads in-range)

    // prologue: fill up to STAGES-1 stages
    const int pre = (F < STAGES - 1) ? F : (STAGES - 1);
    for (int j = 0; j < pre; j++)
        stage_in(obase + (unsigned)j * (NT * 16), tbase + (unsigned)j * (NT * 8),
                 o4, t2, gbase + j * stride);

    for (int k = 0; k < F; k++) {
        asm volatile("cp.async.wait_group 2;" ::: "memory");
        const int slot = k & (STAGES - 1);
        // prefetch first (target slot was freed last iteration), then consume
        if (k + STAGES - 1 < F) {
            const int ns = (k + STAGES - 1) & (STAGES - 1);
            stage_in(obase + (unsigned)ns * (NT * 16), tbase + (unsigned)ns * (NT * 8),
                     o4, t2, gbase + (k + STAGES - 1) * stride);
        }
        float4 p = *(const float4*)(smem + OUTS_OFF + ((slot * NT + tid) << 4));
        uint2  t = *(const uint2*) (smem + TGTS_OFF + ((slot * NT + tid) << 3));
        process(p.y - p.x, t.x, hbase);
        process(p.w - p.z, t.y, hbase);
    }

    // tail pairs not covered by full iterations: direct loads
    for (int i = F * stride + gbase; i < npairs; i += stride) {
        float4 p = __ldcs(o4 + i);
        uint2  t = __ldcs(t2 + i);
        process(p.y - p.x, t.x, hbase);
        process(p.w - p.z, t.y, hbase);
    }
    // odd-n scalar tail — empty for N = 2^24
    for (int s = npairs * 2 + gbase; s < n; s += stride) {
        const float* o = (const float*)o4;
        const unsigned* tg = (const unsigned*)t2;
        process(o[2 * s + 1] - o[2 * s], tg[s], hbase);
    }
    __syncthreads();

    // hist -> warp reduce -> block partials
#pragma unroll
    for (int k = 0; k < NBINS; k++) {
        float2 hv = hist[k * NT + tid];
        float s = hv.x, c = hv.y;
#pragma unroll
        for (int off = 16; off > 0; off >>= 1) {
            s += __shfl_xor_sync(0xffffffffu, s, off);
            c += __shfl_xor_sync(0xffffffffu, c, off);
        }
        if ((tid & 31) == 0) {
            atomicAdd(&s_red[k],         s);
            atomicAdd(&s_red[NBINS + k], c);
        }
    }
    __syncthreads();

    if (tid < NBINS)           atomicAdd(&g_sum[tid],         s_red[tid]);
    else if (tid < 2 * NBINS)  atomicAdd(&g_cnt[tid - NBINS], s_red[tid]);
    __threadfence();
    if (tid == 0) *s_last = (atomicAdd(&g_done, 1u) == (unsigned)(ncta - 1));
    __syncthreads();

    if (*s_last && tid == 0) {
        float res = 0.0f;
#pragma unroll
        for (int b = 0; b < NBINS; b++) {
            float sb = atomicAdd(&g_sum[b], 0.0f);
            float cb = atomicAdd(&g_cnt[b], 0.0f);
            if (cb > 0.0f) {
                float na = 0.75f * acc_sum[b] + 0.25f * cb;
                res += sb * 0.6931471805599453f / na;  // ln2: sums in log2 units
            }
        }
        out[0] = res;
#pragma unroll
        for (int b = 0; b < NBINS; b++) { g_sum[b] = 0.0f; g_cnt[b] = 0.0f; }
        g_done = 0u;
    }
}

extern "C" void kernel_launch(void* const* d_in, const int* in_sizes, int n_in,
                              void* d_out, int out_size) {
    // Identify inputs BY SIZE: outputs = largest (2N f32); acc_sum = 10 f32; targets = rest (N i32)
    int i_out = 0;
    for (int i = 1; i < n_in; i++) if (in_sizes[i] > in_sizes[i_out]) i_out = i;
    int i_acc = -1;
    for (int i = 0; i < n_in; i++) if (i != i_out && in_sizes[i] == NBINS) { i_acc = i; break; }
    if (i_acc < 0) {
        for (int i = 0; i < n_in; i++)
            if (i != i_out && (i_acc < 0 || in_sizes[i] < in_sizes[i_acc])) i_acc = i;
    }
    int i_tgt = 0;
    for (int i = 0; i < n_in; i++) if (i != i_out && i != i_acc) { i_tgt = i; break; }

    const float4* o4  = (const float4*)d_in[i_out];
    const uint2*  t2  = (const uint2*)d_in[i_tgt];
    const float*  acc = (const float*)d_in[i_acc];
    const int n = in_sizes[i_tgt];
    const int npairs = n / 2;

    int sms = 148;
    cudaDeviceGetAttribute(&sms, cudaDevAttrMultiProcessorCount, 0);
    const int ncta = sms * 5;   // 5 CTAs/SM: 5 x 46KB = 230KB <= 228KB-per-SM budget

    cudaFuncSetAttribute(ghm_main, cudaFuncAttributeMaxDynamicSharedMemorySize, SMEM_BYTES);
    ghm_main<<<ncta, NT, SMEM_BYTES>>>(o4, t2, npairs, n, acc, (float*)d_out, ncta);
}

// round 11
// speedup vs baseline: 1.3778x; 1.3778x over previous
#include <cuda_runtime.h>

#define NT      256
#define NBINS   10
#define STAGES  4
#define CHUNK   (NT * 4)            // 1024 samples per CTA-stage

#define OUTS_STAGE (CHUNK * 8)      // 8192 B of outputs per stage
#define TGTS_STAGE (CHUNK * 4)      // 4096 B of targets per stage
#define OUTS_OFF 0
#define TGTS_OFF (STAGES * OUTS_STAGE)             // 32768
#define HIST_OFF (TGTS_OFF + STAGES * TGTS_STAGE)  // 49152
#define RED_OFF  (HIST_OFF + NBINS * NT * 8)       // 69632
#define SMEM_BYTES (RED_OFF + 96)                  // ~68.1 KB -> 3 CTAs/SM

__device__ float    g_sum[NBINS];
__device__ float    g_cnt[NBINS];
__device__ unsigned g_done;

extern __shared__ char smem[];

__device__ __forceinline__ unsigned smem_addr(unsigned off) {
    unsigned base;
    asm("{ .reg .u64 a; cvta.to.shared.u64 a, %1; cvt.u32.u64 %0, a; }"
        : "=r"(base) : "l"((void*)smem));
    return base + off;
}

// Per-sample: d = x_other - x_target
//   v = 1 + e^d ; l = log2(v) ; r = 1/v ; bin = floor(20 - 20r); valid <=> bin < 10
__device__ __forceinline__ void process(float dd, unsigned t, unsigned hbase) {
    float d = __int_as_float(__float_as_int(dd) ^ (int)(t << 31));
    float u; asm("ex2.approx.f32 %0, %1;" : "=f"(u) : "f"(d * 1.4426950408889634f));
    float v = 1.0f + u;
    float l; asm("lg2.approx.f32 %0, %1;" : "=f"(l) : "f"(v));
    float r; asm("rcp.approx.f32 %0, %1;" : "=f"(r) : "f"(v));
    float s = fmaf(-20.0f, r, 20.0f);
    int b = (int)s;                       // trunc; in [0,20]
    unsigned long long lv;
    asm("mov.b64 %0, {%1, %2};" : "=l"(lv) : "f"(l), "f"(1.0f));
    unsigned addr = hbase + ((unsigned)b << 11);
    asm volatile("{\n\t.reg .pred p;\n\t.reg .b64 hv;\n\t"
                 "setp.lt.s32 p, %0, 10;\n\t"
                 "@p ld.shared.b64 hv, [%1];\n\t"
                 "@p add.rn.f32x2 hv, hv, %2;\n\t"
                 "@p st.shared.b64 [%1], hv;\n\t}"
                 :: "r"(b), "r"(addr), "l"(lv) : "memory");
}

// Stage chunk c into slot s: 3 fully-coalesced 16B cp.asyncs per thread.
__device__ __forceinline__ void stage_in(const float4* o4, const uint4* t4q,
                                         int c, int slot, int tid,
                                         unsigned sbase) {
    const unsigned so = sbase + OUTS_OFF + (unsigned)slot * OUTS_STAGE + (unsigned)tid * 16;
    const unsigned st = sbase + TGTS_OFF + (unsigned)slot * TGTS_STAGE + (unsigned)tid * 16;
    const float4* gsrc = o4 + (size_t)c * (CHUNK / 2) + tid;
    asm volatile("cp.async.cg.shared.global [%0], [%1], 16;" :: "r"(so), "l"(gsrc));
    asm volatile("cp.async.cg.shared.global [%0], [%1], 16;"
                 :: "r"(so + NT * 16), "l"(gsrc + NT));
    asm volatile("cp.async.cg.shared.global [%0], [%1], 16;"
                 :: "r"(st), "l"(t4q + (size_t)c * (CHUNK / 4) + tid));
    asm volatile("cp.async.commit_group;" ::: "memory");
}

__global__ void __launch_bounds__(NT)
ghm_main(const float4* __restrict__ o4, const uint4* __restrict__ t4q,
         int nchunks, int n, const float* __restrict__ acc_sum,
         float* __restrict__ out, int ncta) {
    const int tid = threadIdx.x;

    float*    s_red  = (float*)(smem + RED_OFF);
    unsigned* s_last = (unsigned*)(smem + RED_OFF + 80);
    float2*   hist   = (float2*)(smem + HIST_OFF);

    if (tid < 2 * NBINS) s_red[tid] = 0.0f;
#pragma unroll
    for (int k = 0; k < NBINS; k++) hist[k * NT + tid] = make_float2(0.0f, 0.0f);
    __syncthreads();

    const unsigned sbase = smem_addr(0);
    const unsigned hbase = sbase + HIST_OFF + tid * 8;

    const int bx = blockIdx.x, g = gridDim.x;
    const int myChunks = (nchunks > bx) ? (nchunks - bx + g - 1) / g : 0;

    // prologue: fill up to STAGES-1 stages
    const int pre = (myChunks < STAGES - 1) ? myChunks : (STAGES - 1);
    for (int j = 0; j < pre; j++)
        stage_in(o4, t4q, bx + j * g, j, tid, sbase);

    for (int k = 0; k < myChunks; k++) {
        asm volatile("cp.async.wait_group 2;" ::: "memory");
        const int slot = k & (STAGES - 1);
        const unsigned ob = sbase + OUTS_OFF + (unsigned)slot * OUTS_STAGE;
        const unsigned tb = sbase + TGTS_OFF + (unsigned)slot * TGTS_STAGE;
        // conflict-free consumes: 16B / 8B lane stride
        float4 p = *(const float4*)(smem + (ob - sbase) + tid * 16);
        float4 q = *(const float4*)(smem + (ob - sbase) + (NT + tid) * 16);
        uint2  a = *(const uint2*) (smem + (tb - sbase) + tid * 8);
        uint2  b = *(const uint2*) (smem + (tb - sbase) + (NT + tid) * 8);
        if (k + STAGES - 1 < myChunks)
            stage_in(o4, t4q, bx + (k + STAGES - 1) * g, (k + STAGES - 1) & (STAGES - 1),
                     tid, sbase);
        // 4 independent sample chains
        process(p.y - p.x, a.x, hbase);
        process(p.w - p.z, a.y, hbase);
        process(q.y - q.x, b.x, hbase);
        process(q.w - q.z, b.y, hbase);
    }

    // tail: samples not covered by full chunks — direct loads
    const int gthreads = g * NT;
    for (int s = nchunks * CHUNK + bx * NT + tid; s < n; s += gthreads) {
        const float* o = (const float*)o4;
        const unsigned* tg = (const unsigned*)t4q;
        process(o[2 * s + 1] - o[2 * s], tg[s], hbase);
    }
    __syncthreads();

    // hist -> warp reduce -> block partials
#pragma unroll
    for (int k = 0; k < NBINS; k++) {
        float2 hv = hist[k * NT + tid];
        float s = hv.x, c = hv.y;
#pragma unroll
        for (int off = 16; off > 0; off >>= 1) {
            s += __shfl_xor_sync(0xffffffffu, s, off);
            c += __shfl_xor_sync(0xffffffffu, c, off);
        }
        if ((tid & 31) == 0) {
            atomicAdd(&s_red[k],         s);
            atomicAdd(&s_red[NBINS + k], c);
        }
    }
    __syncthreads();

    if (tid < NBINS)           atomicAdd(&g_sum[tid],         s_red[tid]);
    else if (tid < 2 * NBINS)  atomicAdd(&g_cnt[tid - NBINS], s_red[tid]);
    __threadfence();
    if (tid == 0) *s_last = (atomicAdd(&g_done, 1u) == (unsigned)(ncta - 1));
    __syncthreads();

    if (*s_last && tid == 0) {
        float res = 0.0f;
#pragma unroll
        for (int b = 0; b < NBINS; b++) {
            float sb = atomicAdd(&g_sum[b], 0.0f);
            float cb = atomicAdd(&g_cnt[b], 0.0f);
            if (cb > 0.0f) {
                float na = 0.75f * acc_sum[b] + 0.25f * cb;
                res += sb * 0.6931471805599453f / na;  // ln2: sums in log2 units
            }
        }
        out[0] = res;
#pragma unroll
        for (int b = 0; b < NBINS; b++) { g_sum[b] = 0.0f; g_cnt[b] = 0.0f; }
        g_done = 0u;
    }
}

extern "C" void kernel_launch(void* const* d_in, const int* in_sizes, int n_in,
                              void* d_out, int out_size) {
    // Identify inputs BY SIZE: outputs = largest (2N f32); acc_sum = 10 f32; targets = rest (N i32)
    int i_out = 0;
    for (int i = 1; i < n_in; i++) if (in_sizes[i] > in_sizes[i_out]) i_out = i;
    int i_acc = -1;
    for (int i = 0; i < n_in; i++) if (i != i_out && in_sizes[i] == NBINS) { i_acc = i; break; }
    if (i_acc < 0) {
        for (int i = 0; i < n_in; i++)
            if (i != i_out && (i_acc < 0 || in_sizes[i] < in_sizes[i_acc])) i_acc = i;
    }
    int i_tgt = 0;
    for (int i = 0; i < n_in; i++) if (i != i_out && i != i_acc) { i_tgt = i; break; }

    const float4* o4  = (const float4*)d_in[i_out];
    const uint4*  t4q = (const uint4*)d_in[i_tgt];
    const float*  acc = (const float*)d_in[i_acc];
    const int n = in_sizes[i_tgt];
    const int nchunks = n / CHUNK;

    int sms = 148;
    cudaDeviceGetAttribute(&sms, cudaDevAttrMultiProcessorCount, 0);
    const int ncta = sms * 3;   // 3 CTAs/SM at ~68 KB smem each

    cudaFuncSetAttribute(ghm_main, cudaFuncAttributeMaxDynamicSharedMemorySize, SMEM_BYTES);
    ghm_main<<<ncta, NT, SMEM_BYTES>>>(o4, t4q, nchunks, n, acc, (float*)d_out, ncta);
}